// round 6
// baseline (speedup 1.0000x reference)
#include <cuda_runtime.h>
#include <cstdint>

// Problem constants
#define CCk 128
#define DDk 32
#define SSk 4096

// ---------------- smem byte layout ----------------
// Stages (both phases): stage s at s*32KB: hi [128][64] bf16 (16KB) + lo (+16KB).
// E f32 [128][132] at 64KB (67584 B).
// A_hi at 133120: two 16KB blocks by (m>>6).
// inv[128] f32 at 165888.
#define STAGE(s)  ((uint32_t)(s) * 32768u)
#define EOFF      65536u
#define ESTRIDE   132
#define AOFF      133120u
#define IVOFF     165888u
#define SMEMSZ    (IVOFF + 512u)

#define SWZ(o) ((o) ^ (((o) >> 3) & 0x70u))

static __device__ __forceinline__ uint32_t s2u(const void* p) {
    uint32_t a;
    asm("{ .reg .u64 t; cvta.to.shared.u64 t, %1; cvt.u32.u64 %0, t; }"
        : "=r"(a) : "l"(p));
    return a;
}

static __device__ __forceinline__ void ldsm4(uint32_t* r, uint32_t addr) {
    asm volatile("ldmatrix.sync.aligned.m8n8.x4.shared.b16 {%0,%1,%2,%3}, [%4];"
        : "=r"(r[0]), "=r"(r[1]), "=r"(r[2]), "=r"(r[3]) : "r"(addr));
}
static __device__ __forceinline__ void ldsm4t(uint32_t* r, uint32_t addr) {
    asm volatile("ldmatrix.sync.aligned.m8n8.x4.trans.shared.b16 {%0,%1,%2,%3}, [%4];"
        : "=r"(r[0]), "=r"(r[1]), "=r"(r[2]), "=r"(r[3]) : "r"(addr));
}
static __device__ __forceinline__ void mma16816(float* c, const uint32_t* a,
                                                uint32_t b0, uint32_t b1) {
    asm volatile(
        "mma.sync.aligned.m16n8k16.row.col.f32.bf16.bf16.f32 "
        "{%0,%1,%2,%3}, {%4,%5,%6,%7}, {%8,%9}, {%0,%1,%2,%3};"
        : "+f"(c[0]), "+f"(c[1]), "+f"(c[2]), "+f"(c[3])
        : "r"(a[0]), "r"(a[1]), "r"(a[2]), "r"(a[3]), "r"(b0), "r"(b1));
}

static __device__ __forceinline__ void split2(float f0, float f1, uint32_t& hp, uint32_t& lp) {
    asm("cvt.rn.bf16x2.f32 %0, %1, %2;" : "=r"(hp) : "f"(f1), "f"(f0));
    float h0 = __uint_as_float(hp << 16);
    float h1 = __uint_as_float(hp & 0xffff0000u);
    asm("cvt.rn.bf16x2.f32 %0, %1, %2;" : "=r"(lp) : "f"(f1 - h1), "f"(f0 - h0));
}
static __device__ __forceinline__ uint32_t pack2hi(float f0, float f1) {
    uint32_t hp;
    asm("cvt.rn.bf16x2.f32 %0, %1, %2;" : "=r"(hp) : "f"(f1), "f"(f0));
    return hp;
}
static __device__ __forceinline__ void split8(float4 a, float4 b, uint4& hi, uint4& lo) {
    split2(a.x, a.y, hi.x, lo.x);
    split2(a.z, a.w, hi.y, lo.y);
    split2(b.x, b.y, hi.z, lo.z);
    split2(b.z, b.w, hi.w, lo.w);
}
static __device__ __forceinline__ float2 bfpair(uint32_t w) {
    float2 r;
    r.x = __uint_as_float(w << 16);
    r.y = __uint_as_float(w & 0xffff0000u);
    return r;
}

__global__ __launch_bounds__(256, 1)
void cam_mma2_kernel(const float* __restrict__ x,
                     const float* __restrict__ gamma,
                     float* __restrict__ out)
{
    extern __shared__ __align__(1024) uint8_t sm[];
    const uint32_t smb = s2u(sm);

    const int tid  = threadIdx.x;
    const int lane = tid & 31;
    const int wid  = tid >> 5;

    const int n = blockIdx.x;
    const int b = n / DDk, d = n % DDk;
    const float* xbase = x + ((size_t)(b * CCk) * DDk + d) * (size_t)SSk;
    const size_t cstride = (size_t)DDk * SSk;
    float* outbase = out + (size_t)n * CCk * SSk;

    // =============== Phase 1: E = V*V^T. Consumers: warps 0-3 (64x64 tiles). ===============
    //                 Producers: warps 4-7 convert f32 -> bf16 hi/lo tiles.
    const bool producer = (wid >= 4);
    const int prow = tid - 128;                       // producer row (0..127)
    const float* prowp = xbase + (size_t)(prow & 127) * cstride;

    const int m0 = (wid & 1) * 64;
    const int n0 = ((wid >> 1) & 1) * 64;

    float acc[4][8][4];
#pragma unroll
    for (int mt = 0; mt < 4; mt++)
#pragma unroll
        for (int nt = 0; nt < 8; nt++)
#pragma unroll
            for (int q = 0; q < 4; q++) acc[mt][nt][q] = 0.f;

    float4 pf[16];
    if (producer) {
#pragma unroll
        for (int p = 0; p < 16; p++)
            pf[p] = *reinterpret_cast<const float4*>(prowp + p * 4);
    }

    for (int kc = 0; kc < 64; kc++) {
        const uint32_t hbu = smb + STAGE(kc & 1);
        const uint32_t lbu = hbu + 16384u;
        if (producer) {
            uint8_t* hb = sm + STAGE(kc & 1);
            uint8_t* lb = hb + 16384;
#pragma unroll
            for (int g = 0; g < 8; g++) {
                uint4 hi4, lo4;
                split8(pf[2 * g], pf[2 * g + 1], hi4, lo4);
                uint32_t off = SWZ((uint32_t)(prow * 128 + g * 16));
                *reinterpret_cast<uint4*>(hb + off) = hi4;
                *reinterpret_cast<uint4*>(lb + off) = lo4;
            }
        }
        __syncthreads();
        if (producer && kc + 1 < 64) {
#pragma unroll
            for (int p = 0; p < 16; p++)
                pf[p] = *reinterpret_cast<const float4*>(prowp + (kc + 1) * 64 + p * 4);
        }
        if (!producer) {
#pragma unroll
            for (int kk = 0; kk < 4; kk++) {
                uint32_t ah[4][4], al[4][4];
#pragma unroll
                for (int mt = 0; mt < 4; mt++) {
                    int rowA = m0 + mt * 16 + (lane & 15);
                    int ch = kk * 2 + (lane >> 4);
                    uint32_t off = SWZ((uint32_t)(rowA * 128 + ch * 16));
                    ldsm4(ah[mt], hbu + off);
                    ldsm4(al[mt], lbu + off);
                }
#pragma unroll
                for (int bt = 0; bt < 4; bt++) {
                    uint32_t bh[4], bl[4];
                    int rowB = n0 + bt * 16 + ((lane >> 4) & 1) * 8 + (lane & 7);
                    int chb = kk * 2 + ((lane >> 3) & 1);
                    uint32_t off = SWZ((uint32_t)(rowB * 128 + chb * 16));
                    ldsm4(bh, hbu + off);
                    ldsm4(bl, lbu + off);
#pragma unroll
                    for (int mt = 0; mt < 4; mt++)
#pragma unroll
                        for (int nn = 0; nn < 2; nn++) {
                            float* a4 = acc[mt][bt * 2 + nn];
                            mma16816(a4, ah[mt], bh[nn * 2], bh[nn * 2 + 1]);
                            mma16816(a4, ah[mt], bl[nn * 2], bl[nn * 2 + 1]);
                            mma16816(a4, al[mt], bh[nn * 2], bh[nn * 2 + 1]);
                        }
                }
            }
        }
    }

    // spill E (consumers only)
    if (!producer) {
        float* E = reinterpret_cast<float*>(sm + EOFF);
#pragma unroll
        for (int mt = 0; mt < 4; mt++)
#pragma unroll
            for (int nt = 0; nt < 8; nt++) {
                int row = m0 + mt * 16 + (lane >> 2);
                int col = n0 + nt * 8 + (lane & 3) * 2;
                *reinterpret_cast<float2*>(&E[row * ESTRIDE + col]) =
                    make_float2(acc[mt][nt][0], acc[mt][nt][1]);
                *reinterpret_cast<float2*>(&E[(row + 8) * ESTRIDE + col]) =
                    make_float2(acc[mt][nt][2], acc[mt][nt][3]);
            }
    }
    __syncthreads();

    // prefetch phase-2 chunk 0 (all threads) while softmin runs
    const int r2 = tid >> 1, h2 = tid & 1;
    const float* rowp2 = xbase + (size_t)r2 * cstride;
    float4 pf2[8];
#pragma unroll
    for (int p = 0; p < 8; p++)
        pf2[p] = *reinterpret_cast<const float4*>(rowp2 + h2 * 32 + p * 4);

    // =============== Softmin: A_hi[c][m] = bf16(exp(min_c - E[c][m])) ===============
    if (tid < 128) {
        const int c = tid;
        const float* Er = reinterpret_cast<const float*>(sm + EOFF) + c * ESTRIDE;
        float mn = Er[0];
#pragma unroll 4
        for (int m = 1; m < 128; m++) mn = fminf(mn, Er[m]);
        float sum = 0.f;
#pragma unroll
        for (int mg = 0; mg < 16; mg++) {
            float p[8];
#pragma unroll
            for (int q = 0; q < 8; q++) {
                p[q] = __expf(mn - Er[mg * 8 + q]);
                sum += p[q];
            }
            uint4 hi4;
            hi4.x = pack2hi(p[0], p[1]);
            hi4.y = pack2hi(p[2], p[3]);
            hi4.z = pack2hi(p[4], p[5]);
            hi4.w = pack2hi(p[6], p[7]);
            const int m = mg * 8;
            uint32_t off = AOFF + (uint32_t)(m >> 6) * 16384u
                         + SWZ((uint32_t)(c * 128 + (m & 63) * 2));
            *reinterpret_cast<uint4*>(sm + off) = hi4;
        }
        reinterpret_cast<float*>(sm + IVOFF)[c] = gamma[0] / sum;
    }
    __syncthreads();

    // =============== Phase 2: out = A*V. 8 warps, 32x32 tiles, A_hi in regs ===============
    const int wm = wid & 3;
    const int wn = wid >> 2;
    const int p2m0 = wm * 32;

    uint32_t ahr[2][8][4];
#pragma unroll
    for (int mt = 0; mt < 2; mt++)
#pragma unroll
        for (int kk = 0; kk < 8; kk++) {
            int rowA = p2m0 + mt * 16 + (lane & 15);
            int chb = (kk & 3) * 2 + (lane >> 4);
            uint32_t off = AOFF + (uint32_t)(kk >> 2) * 16384u
                         + SWZ((uint32_t)(rowA * 128 + chb * 16));
            ldsm4(ahr[mt][kk], smb + off);
        }

    for (int sc = 0; sc < 64; sc++) {
        uint8_t* hb = sm + STAGE(sc & 1);
        uint8_t* lb = hb + 16384;
#pragma unroll
        for (int g = 0; g < 4; g++) {
            uint4 hi4, lo4;
            split8(pf2[2 * g], pf2[2 * g + 1], hi4, lo4);
            uint32_t off = SWZ((uint32_t)(r2 * 128 + h2 * 64 + g * 16));
            *reinterpret_cast<uint4*>(hb + off) = hi4;
            *reinterpret_cast<uint4*>(lb + off) = lo4;
        }
        __syncthreads();
        if (sc + 1 < 64) {
#pragma unroll
            for (int p = 0; p < 8; p++)
                pf2[p] = *reinterpret_cast<const float4*>(rowp2 + (sc + 1) * 64 + h2 * 32 + p * 4);
        }

        float c2[2][4][4];
#pragma unroll
        for (int mt = 0; mt < 2; mt++)
#pragma unroll
            for (int nt = 0; nt < 4; nt++)
#pragma unroll
                for (int q = 0; q < 4; q++) c2[mt][nt][q] = 0.f;

        const uint32_t Bh = smb + STAGE(sc & 1);
        const uint32_t Bl = Bh + 16384u;
#pragma unroll
        for (int kk = 0; kk < 8; kk++) {
            uint32_t bh[2][4], bl[2][4];
#pragma unroll
            for (int bt = 0; bt < 2; bt++) {
                int rowB = kk * 16 + (lane & 15);
                int sch = wn * 4 + bt * 2 + (lane >> 4);
                uint32_t off = SWZ((uint32_t)(rowB * 128 + sch * 16));
                ldsm4t(bh[bt], Bh + off);
                ldsm4t(bl[bt], Bl + off);
            }
#pragma unroll
            for (int mt = 0; mt < 2; mt++)
#pragma unroll
                for (int nt = 0; nt < 4; nt++) {
                    uint32_t b0h = bh[nt >> 1][(nt & 1) * 2];
                    uint32_t b1h = bh[nt >> 1][(nt & 1) * 2 + 1];
                    uint32_t b0l = bl[nt >> 1][(nt & 1) * 2];
                    uint32_t b1l = bl[nt >> 1][(nt & 1) * 2 + 1];
                    mma16816(c2[mt][nt], ahr[mt][kk], b0h, b1h);
                    mma16816(c2[mt][nt], ahr[mt][kk], b0l, b1l);
                }
        }

        // epilogue: out[c][s] = inv[c]*acc + V[c][s]
        const float* ivp = reinterpret_cast<const float*>(sm + IVOFF);
#pragma unroll
        for (int mt = 0; mt < 2; mt++)
#pragma unroll
            for (int nt = 0; nt < 4; nt++) {
                int row = p2m0 + mt * 16 + (lane >> 2);
                int scol = wn * 32 + nt * 8 + (lane & 3) * 2;
#pragma unroll
                for (int half = 0; half < 2; half++) {
                    int c = row + half * 8;
                    float iv = ivp[c];
                    uint32_t offv = SWZ((uint32_t)(c * 128 + scol * 2));
                    float2 vh = bfpair(*reinterpret_cast<const uint32_t*>(hb + offv));
                    float2 vl = bfpair(*reinterpret_cast<const uint32_t*>(lb + offv));
                    float2 o;
                    o.x = fmaf(c2[mt][nt][half * 2 + 0], iv, vh.x + vl.x);
                    o.y = fmaf(c2[mt][nt][half * 2 + 1], iv, vh.y + vl.y);
                    *reinterpret_cast<float2*>(outbase + (size_t)c * SSk + sc * 64 + scol) = o;
                }
            }
    }
}

extern "C" void kernel_launch(void* const* d_in, const int* in_sizes, int n_in,
                              void* d_out, int out_size)
{
    const float* x     = (const float*)d_in[0];
    const float* gamma = (const float*)d_in[1];
    float* out = (float*)d_out;

    cudaFuncSetAttribute(cam_mma2_kernel,
                         cudaFuncAttributeMaxDynamicSharedMemorySize, SMEMSZ);
    cam_mma2_kernel<<<128, 256, SMEMSZ>>>(x, gamma, out);
}

// round 7
// speedup vs baseline: 1.1686x; 1.1686x over previous
#include <cuda_runtime.h>
#include <cstdint>

// Problem constants
#define CCk 128
#define DDk 32
#define SSk 4096

// ---------------- smem byte layout ----------------
// Stages (both phases): stage s at s*32KB: hi [128][64] bf16 (16KB) + lo (+16KB).
// E f32 [128][132] at 64KB.
// A_hi at 133120: two 16KB blocks by (m>>6).
// inv[128] f32 at 165888.
#define STAGE(s)  ((uint32_t)(s) * 32768u)
#define EOFF      65536u
#define ESTRIDE   132
#define AOFF      133120u
#define IVOFF     165888u
#define SMEMSZ    (IVOFF + 512u)

#define SWZ(o) ((o) ^ (((o) >> 3) & 0x70u))

static __device__ __forceinline__ uint32_t s2u(const void* p) {
    uint32_t a;
    asm("{ .reg .u64 t; cvta.to.shared.u64 t, %1; cvt.u32.u64 %0, t; }"
        : "=r"(a) : "l"(p));
    return a;
}

static __device__ __forceinline__ void ldsm4(uint32_t* r, uint32_t addr) {
    asm volatile("ldmatrix.sync.aligned.m8n8.x4.shared.b16 {%0,%1,%2,%3}, [%4];"
        : "=r"(r[0]), "=r"(r[1]), "=r"(r[2]), "=r"(r[3]) : "r"(addr));
}
static __device__ __forceinline__ void ldsm4t(uint32_t* r, uint32_t addr) {
    asm volatile("ldmatrix.sync.aligned.m8n8.x4.trans.shared.b16 {%0,%1,%2,%3}, [%4];"
        : "=r"(r[0]), "=r"(r[1]), "=r"(r[2]), "=r"(r[3]) : "r"(addr));
}
static __device__ __forceinline__ void mma16816(float* c, const uint32_t* a,
                                                uint32_t b0, uint32_t b1) {
    asm volatile(
        "mma.sync.aligned.m16n8k16.row.col.f32.bf16.bf16.f32 "
        "{%0,%1,%2,%3}, {%4,%5,%6,%7}, {%8,%9}, {%0,%1,%2,%3};"
        : "+f"(c[0]), "+f"(c[1]), "+f"(c[2]), "+f"(c[3])
        : "r"(a[0]), "r"(a[1]), "r"(a[2]), "r"(a[3]), "r"(b0), "r"(b1));
}

static __device__ __forceinline__ void split2(float f0, float f1, uint32_t& hp, uint32_t& lp) {
    asm("cvt.rn.bf16x2.f32 %0, %1, %2;" : "=r"(hp) : "f"(f1), "f"(f0));
    float h0 = __uint_as_float(hp << 16);
    float h1 = __uint_as_float(hp & 0xffff0000u);
    asm("cvt.rn.bf16x2.f32 %0, %1, %2;" : "=r"(lp) : "f"(f1 - h1), "f"(f0 - h0));
}
static __device__ __forceinline__ uint32_t pack2hi(float f0, float f1) {
    uint32_t hp;
    asm("cvt.rn.bf16x2.f32 %0, %1, %2;" : "=r"(hp) : "f"(f1), "f"(f0));
    return hp;
}
static __device__ __forceinline__ void split8(float4 a, float4 b, uint4& hi, uint4& lo) {
    split2(a.x, a.y, hi.x, lo.x);
    split2(a.z, a.w, hi.y, lo.y);
    split2(b.x, b.y, hi.z, lo.z);
    split2(b.z, b.w, hi.w, lo.w);
}
static __device__ __forceinline__ float2 bfpair(uint32_t w) {
    float2 r;
    r.x = __uint_as_float(w << 16);
    r.y = __uint_as_float(w & 0xffff0000u);
    return r;
}

__global__ __launch_bounds__(256, 1)
void cam_mma3_kernel(const float* __restrict__ x,
                     const float* __restrict__ gamma,
                     float* __restrict__ out)
{
    extern __shared__ __align__(1024) uint8_t sm[];
    const uint32_t smb = s2u(sm);

    const int tid  = threadIdx.x;
    const int lane = tid & 31;
    const int wid  = tid >> 5;
    const int wm   = wid & 3;      // m block: rows 32*wm
    const int wn   = wid >> 2;     // n block
    const int m0   = wm * 32;

    const int n = blockIdx.x;
    const int b = n / DDk, d = n % DDk;
    const float* xbase = x + ((size_t)(b * CCk) * DDk + d) * (size_t)SSk;
    const size_t cstride = (size_t)DDk * SSk;
    float* outbase = out + (size_t)n * CCk * SSk;

    const int r = tid >> 1, h = tid & 1;   // conversion mapping: row r, half h
    const float* rowp = xbase + (size_t)r * cstride;

    // =============== Phase 1: E = V * V^T (K = 4096, chunks of 64), 3-term ===============
    float acc[2][8][4];
#pragma unroll
    for (int mt = 0; mt < 2; mt++)
#pragma unroll
        for (int nt = 0; nt < 8; nt++)
#pragma unroll
            for (int q = 0; q < 4; q++) acc[mt][nt][q] = 0.f;

    const int n0 = wn * 64;

    float4 pf[8];
#pragma unroll
    for (int p = 0; p < 8; p++)
        pf[p] = *reinterpret_cast<const float4*>(rowp + h * 32 + p * 4);

    for (int kc = 0; kc < 64; kc++) {
        uint8_t* hb = sm + STAGE(kc & 1);
        uint8_t* lb = hb + 16384;
#pragma unroll
        for (int g = 0; g < 4; g++) {
            uint4 hi4, lo4;
            split8(pf[2 * g], pf[2 * g + 1], hi4, lo4);
            uint32_t off = SWZ((uint32_t)(r * 128 + h * 64 + g * 16));
            *reinterpret_cast<uint4*>(hb + off) = hi4;
            *reinterpret_cast<uint4*>(lb + off) = lo4;
        }
        __syncthreads();
        if (kc + 1 < 64) {
#pragma unroll
            for (int p = 0; p < 8; p++)
                pf[p] = *reinterpret_cast<const float4*>(rowp + (kc + 1) * 64 + h * 32 + p * 4);
        }
        const uint32_t hbu = smb + STAGE(kc & 1);
        const uint32_t lbu = hbu + 16384u;
#pragma unroll
        for (int kk = 0; kk < 4; kk++) {
            uint32_t ah[2][4], al[2][4], bh[4][4], bl[4][4];
#pragma unroll
            for (int mt = 0; mt < 2; mt++) {
                int rowA = m0 + mt * 16 + (lane & 15);
                int ch = kk * 2 + (lane >> 4);
                uint32_t off = SWZ((uint32_t)(rowA * 128 + ch * 16));
                ldsm4(ah[mt], hbu + off);
                ldsm4(al[mt], lbu + off);
            }
#pragma unroll
            for (int bt = 0; bt < 4; bt++) {
                int rowB = n0 + bt * 16 + ((lane >> 4) & 1) * 8 + (lane & 7);
                int ch = kk * 2 + ((lane >> 3) & 1);
                uint32_t off = SWZ((uint32_t)(rowB * 128 + ch * 16));
                ldsm4(bh[bt], hbu + off);
                ldsm4(bl[bt], lbu + off);
            }
#pragma unroll
            for (int mt = 0; mt < 2; mt++)
#pragma unroll
                for (int nt = 0; nt < 8; nt++) {
                    uint32_t b0h = bh[nt >> 1][(nt & 1) * 2];
                    uint32_t b1h = bh[nt >> 1][(nt & 1) * 2 + 1];
                    uint32_t b0l = bl[nt >> 1][(nt & 1) * 2];
                    uint32_t b1l = bl[nt >> 1][(nt & 1) * 2 + 1];
                    mma16816(acc[mt][nt], ah[mt], b0h, b1h);
                    mma16816(acc[mt][nt], ah[mt], b0l, b1l);
                    mma16816(acc[mt][nt], al[mt], b0h, b1h);
                }
        }
    }

    // spill E to smem
    {
        float* E = reinterpret_cast<float*>(sm + EOFF);
#pragma unroll
        for (int mt = 0; mt < 2; mt++)
#pragma unroll
            for (int nt = 0; nt < 8; nt++) {
                int row = m0 + mt * 16 + (lane >> 2);
                int col = n0 + nt * 8 + (lane & 3) * 2;
                *reinterpret_cast<float2*>(&E[row * ESTRIDE + col]) =
                    make_float2(acc[mt][nt][0], acc[mt][nt][1]);
                *reinterpret_cast<float2*>(&E[(row + 8) * ESTRIDE + col]) =
                    make_float2(acc[mt][nt][2], acc[mt][nt][3]);
            }
    }
    __syncthreads();

    // prefetch phase-2 chunk 0 while softmin runs
    float4 pf2[8];
#pragma unroll
    for (int p = 0; p < 8; p++)
        pf2[p] = *reinterpret_cast<const float4*>(rowp + h * 32 + p * 4);

    // =============== Softmin: A_hi[c][m] = bf16(exp(min_c - E[c][m])) ===============
    if (tid < 128) {
        const int c = tid;
        const float* Er = reinterpret_cast<const float*>(sm + EOFF) + c * ESTRIDE;
        float mn = Er[0];
#pragma unroll 4
        for (int m = 1; m < 128; m++) mn = fminf(mn, Er[m]);
        float sum = 0.f;
#pragma unroll
        for (int mg = 0; mg < 16; mg++) {
            float p[8];
#pragma unroll
            for (int q = 0; q < 8; q++) {
                p[q] = __expf(mn - Er[mg * 8 + q]);
                sum += p[q];
            }
            uint4 hi4;
            hi4.x = pack2hi(p[0], p[1]);
            hi4.y = pack2hi(p[2], p[3]);
            hi4.z = pack2hi(p[4], p[5]);
            hi4.w = pack2hi(p[6], p[7]);
            const int m = mg * 8;
            uint32_t off = AOFF + (uint32_t)(m >> 6) * 16384u
                         + SWZ((uint32_t)(c * 128 + (m & 63) * 2));
            *reinterpret_cast<uint4*>(sm + off) = hi4;
        }
        reinterpret_cast<float*>(sm + IVOFF)[c] = gamma[0] / sum;
    }
    __syncthreads();

    // =============== Phase 2: out = A_hi * V_hi. A in registers, 1-term ===============
    uint32_t ahr[2][8][4];
#pragma unroll
    for (int mt = 0; mt < 2; mt++)
#pragma unroll
        for (int kk = 0; kk < 8; kk++) {
            int rowA = m0 + mt * 16 + (lane & 15);
            int chb = (kk & 3) * 2 + (lane >> 4);
            uint32_t off = AOFF + (uint32_t)(kk >> 2) * 16384u
                         + SWZ((uint32_t)(rowA * 128 + chb * 16));
            ldsm4(ahr[mt][kk], smb + off);
        }

    for (int sc = 0; sc < 64; sc++) {
        uint8_t* hb = sm + STAGE(sc & 1);
        uint8_t* lb = hb + 16384;
#pragma unroll
        for (int g = 0; g < 4; g++) {
            uint4 hi4, lo4;
            split8(pf2[2 * g], pf2[2 * g + 1], hi4, lo4);
            uint32_t off = SWZ((uint32_t)(r * 128 + h * 64 + g * 16));
            *reinterpret_cast<uint4*>(hb + off) = hi4;
            *reinterpret_cast<uint4*>(lb + off) = lo4;
        }
        __syncthreads();
        if (sc + 1 < 64) {
#pragma unroll
            for (int p = 0; p < 8; p++)
                pf2[p] = *reinterpret_cast<const float4*>(rowp + (sc + 1) * 64 + h * 32 + p * 4);
        }

        float c2[2][4][4];
#pragma unroll
        for (int mt = 0; mt < 2; mt++)
#pragma unroll
            for (int nt = 0; nt < 4; nt++)
#pragma unroll
                for (int q = 0; q < 4; q++) c2[mt][nt][q] = 0.f;

        const uint32_t Bh = smb + STAGE(sc & 1);
#pragma unroll
        for (int kk = 0; kk < 8; kk++) {
            uint32_t bh[2][4];
#pragma unroll
            for (int bt = 0; bt < 2; bt++) {
                int rowB = kk * 16 + (lane & 15);
                int sch = wn * 4 + bt * 2 + (lane >> 4);
                uint32_t off = SWZ((uint32_t)(rowB * 128 + sch * 16));
                ldsm4t(bh[bt], Bh + off);
            }
#pragma unroll
            for (int mt = 0; mt < 2; mt++)
#pragma unroll
                for (int nt = 0; nt < 4; nt++)
                    mma16816(c2[mt][nt], ahr[mt][kk],
                             bh[nt >> 1][(nt & 1) * 2], bh[nt >> 1][(nt & 1) * 2 + 1]);
        }

        // epilogue: out[c][s] = inv[c]*acc + V[c][s]  (V = hi + lo, near-exact)
        const float* ivp = reinterpret_cast<const float*>(sm + IVOFF);
#pragma unroll
        for (int mt = 0; mt < 2; mt++)
#pragma unroll
            for (int nt = 0; nt < 4; nt++) {
                int row = m0 + mt * 16 + (lane >> 2);
                int scol = wn * 32 + nt * 8 + (lane & 3) * 2;
#pragma unroll
                for (int half = 0; half < 2; half++) {
                    int c = row + half * 8;
                    float iv = ivp[c];
                    uint32_t offv = SWZ((uint32_t)(c * 128 + scol * 2));
                    float2 vh = bfpair(*reinterpret_cast<const uint32_t*>(hb + offv));
                    float2 vl = bfpair(*reinterpret_cast<const uint32_t*>(lb + offv));
                    float2 o;
                    o.x = fmaf(c2[mt][nt][half * 2 + 0], iv, vh.x + vl.x);
                    o.y = fmaf(c2[mt][nt][half * 2 + 1], iv, vh.y + vl.y);
                    *reinterpret_cast<float2*>(outbase + (size_t)c * SSk + sc * 64 + scol) = o;
                }
            }
    }
}

extern "C" void kernel_launch(void* const* d_in, const int* in_sizes, int n_in,
                              void* d_out, int out_size)
{
    const float* x     = (const float*)d_in[0];
    const float* gamma = (const float*)d_in[1];
    float* out = (float*)d_out;

    cudaFuncSetAttribute(cam_mma3_kernel,
                         cudaFuncAttributeMaxDynamicSharedMemorySize, SMEMSZ);
    cam_mma3_kernel<<<128, 256, SMEMSZ>>>(x, gamma, out);
}